// round 3
// baseline (speedup 1.0000x reference)
#include <cuda_runtime.h>
#include <cstdint>

#define NROWS 409600
#define NIN   51200
#define NSEG  65536
#define DIM   512

// ---------------- scratch (static __device__ arrays: alloc-free rule) ----------
__device__ int   g_is64;
__device__ int   g_counts[NSEG];
__device__ int   g_offsets[NSEG];
__device__ int   g_cursor[NSEG];
__device__ int   g_perm[NROWS];
__device__ float g_agg[(size_t)NSEG * DIM];     // 134 MB, tf32-rounded
__device__ float g_linw[DIM * DIM];             // tf32-rounded copy of lin_w

// ---------------- helpers ----------------
__device__ __forceinline__ float rna_tf32(float x) {
    uint32_t r;
    asm("cvt.rna.tf32.f32 %0, %1;" : "=r"(r) : "f"(x));
    return __uint_as_float(r);
}
__device__ __forceinline__ int load_idx(const void* idx, int i, int is64) {
    if (is64) return (int)((const long long*)idx)[i];
    return ((const int*)idx)[i];
}
__device__ __forceinline__ void cp16(uint32_t smem, const void* gmem) {
    asm volatile("cp.async.cg.shared.global [%0], [%1], 16;"
                 :: "r"(smem), "l"(gmem) : "memory");
}

// ---------------- prep kernels ----------------
__global__ void zero_kernel() {
    int i = blockIdx.x * blockDim.x + threadIdx.x;
    if (i < NSEG) g_counts[i] = 0;
    if (i == 0) g_is64 = 1;
}
// If idx is int64, every odd 32-bit word (high half) is 0 (values < 65536).
__global__ void detect_kernel(const unsigned int* w32) {
    int i = blockIdx.x * blockDim.x + threadIdx.x;   // 1024 threads
    if (w32[2 * i + 1] != 0u) g_is64 = 0;
}
__global__ void hist_kernel(const void* idx) {
    int i = blockIdx.x * blockDim.x + threadIdx.x;
    if (i >= NROWS) return;
    atomicAdd(&g_counts[load_idx(idx, i, g_is64)], 1);
}
__global__ void scan_kernel() {   // single block, 1024 threads, 64 chunks
    __shared__ int wsum[32];
    __shared__ int carry;
    int t = threadIdx.x;
    if (t == 0) carry = 0;
    __syncthreads();
    for (int c = 0; c < NSEG / 1024; c++) {
        int i = c * 1024 + t;
        int v = g_counts[i];
        int x = v;
        #pragma unroll
        for (int o = 1; o < 32; o <<= 1) {
            int y = __shfl_up_sync(0xFFFFFFFFu, x, o);
            if ((t & 31) >= o) x += y;
        }
        if ((t & 31) == 31) wsum[t >> 5] = x;
        __syncthreads();
        if (t < 32) {
            int s = wsum[t];
            #pragma unroll
            for (int o = 1; o < 32; o <<= 1) {
                int y = __shfl_up_sync(0xFFFFFFFFu, s, o);
                if (t >= o) s += y;
            }
            wsum[t] = s;
        }
        __syncthreads();
        int base = (t >= 32) ? wsum[(t >> 5) - 1] : 0;
        int off = carry + (x - v) + base;
        g_offsets[i] = off;
        g_cursor[i]  = off;
        int total = wsum[31];
        __syncthreads();
        if (t == 0) carry += total;
        __syncthreads();
    }
}
__global__ void scatter_kernel(const void* idx) {
    int i = blockIdx.x * blockDim.x + threadIdx.x;
    if (i >= NROWS) return;
    int s = load_idx(idx, i, g_is64);
    int pos = atomicAdd(&g_cursor[s], 1);
    g_perm[pos] = i;
}
__global__ void roundw_kernel(const float* __restrict__ lw) {
    int i = blockIdx.x * blockDim.x + threadIdx.x;
    if (i < DIM * DIM) g_linw[i] = rna_tf32(lw[i]);
}

// ---------------- gather-sum: one warp per segment, deterministic order --------
__global__ void __launch_bounds__(256) gather_kernel(const float* __restrict__ h,
                                                     const float* __restrict__ w) {
    int warp = (blockIdx.x * blockDim.x + threadIdx.x) >> 5;
    int lane = threadIdx.x & 31;
    if (warp >= NSEG) return;
    int start = g_offsets[warp];
    int cnt   = g_counts[warp];
    float4 a0 = {0.f, 0.f, 0.f, 0.f}, a1 = a0, a2 = a0, a3 = a0;
    const float4* hb = (const float4*)h;

    auto accum = [&](int row) {
        float wv = __ldg(&w[row % NIN]);
        const float4* hp = hb + (size_t)row * (DIM / 4);
        float4 v0 = __ldg(hp + lane);
        float4 v1 = __ldg(hp + 32 + lane);
        float4 v2 = __ldg(hp + 64 + lane);
        float4 v3 = __ldg(hp + 96 + lane);
        a0.x = fmaf(wv, v0.x, a0.x); a0.y = fmaf(wv, v0.y, a0.y);
        a0.z = fmaf(wv, v0.z, a0.z); a0.w = fmaf(wv, v0.w, a0.w);
        a1.x = fmaf(wv, v1.x, a1.x); a1.y = fmaf(wv, v1.y, a1.y);
        a1.z = fmaf(wv, v1.z, a1.z); a1.w = fmaf(wv, v1.w, a1.w);
        a2.x = fmaf(wv, v2.x, a2.x); a2.y = fmaf(wv, v2.y, a2.y);
        a2.z = fmaf(wv, v2.z, a2.z); a2.w = fmaf(wv, v2.w, a2.w);
        a3.x = fmaf(wv, v3.x, a3.x); a3.y = fmaf(wv, v3.y, a3.y);
        a3.z = fmaf(wv, v3.z, a3.z); a3.w = fmaf(wv, v3.w, a3.w);
    };

    if (cnt <= 256) {
        // ascending-row min-extraction => replay-deterministic fp32 order
        int vals[8];
        int nslot = (cnt + 31) >> 5;
        #pragma unroll
        for (int t = 0; t < 8; t++) {
            int p = t * 32 + lane;
            vals[t] = (t < nslot && p < cnt) ? g_perm[start + p] : 0x7FFFFFFF;
        }
        for (int it = 0; it < cnt; it++) {
            int m = 0x7FFFFFFF, mt = -1;
            #pragma unroll
            for (int t = 0; t < 8; t++)
                if (vals[t] < m) { m = vals[t]; mt = t; }
            int gm = __reduce_min_sync(0xFFFFFFFFu, m);
            if (m == gm && mt >= 0) vals[mt] = 0x7FFFFFFF;  // rows unique: one owner
            accum(gm);
        }
    } else {
        for (int j = 0; j < cnt; j++) accum(g_perm[start + j]);
    }

    // tf32 RN pre-rounding for the MMA operand
    float4* dst = (float4*)(g_agg + (size_t)warp * DIM);
    float4 o;
    o.x = rna_tf32(a0.x); o.y = rna_tf32(a0.y); o.z = rna_tf32(a0.z); o.w = rna_tf32(a0.w);
    dst[lane] = o;
    o.x = rna_tf32(a1.x); o.y = rna_tf32(a1.y); o.z = rna_tf32(a1.z); o.w = rna_tf32(a1.w);
    dst[32 + lane] = o;
    o.x = rna_tf32(a2.x); o.y = rna_tf32(a2.y); o.z = rna_tf32(a2.z); o.w = rna_tf32(a2.w);
    dst[64 + lane] = o;
    o.x = rna_tf32(a3.x); o.y = rna_tf32(a3.y); o.z = rna_tf32(a3.z); o.w = rna_tf32(a3.w);
    dst[96 + lane] = o;
}

// ---------------- tf32 mma.sync GEMM: out = agg @ lin_w^T + b -------------------
// BM=128, BN=128, BK=32. Smem tiles padded to 36-word rows (conflict-free frags).
#define BK 32
#define PADW 36
#define TILEW (128 * PADW)                 // words per tile buffer
#define SMEM_WORDS (4 * TILEW)             // As[2] + Bs[2]
#define SMEM_BYTES (SMEM_WORDS * 4)

__device__ __forceinline__ void mma_tf32(float& d0, float& d1, float& d2, float& d3,
                                         uint32_t a0, uint32_t a1, uint32_t a2, uint32_t a3,
                                         uint32_t b0, uint32_t b1) {
    asm volatile(
        "mma.sync.aligned.m16n8k8.row.col.f32.tf32.tf32.f32 "
        "{%0,%1,%2,%3}, {%4,%5,%6,%7}, {%8,%9}, {%0,%1,%2,%3};"
        : "+f"(d0), "+f"(d1), "+f"(d2), "+f"(d3)
        : "r"(a0), "r"(a1), "r"(a2), "r"(a3), "r"(b0), "r"(b1));
}

__global__ void __launch_bounds__(256, 2)
gemm_kernel(const float* __restrict__ linb, float* __restrict__ out) {
    extern __shared__ float sm[];
    int tid = threadIdx.x, lane = tid & 31, wid = tid >> 5;
    int mtile = blockIdx.x, ntile = blockIdx.y;
    const float* Ag = g_agg  + (size_t)mtile * 128 * DIM;
    const float* Bg = g_linw + (size_t)ntile * 128 * DIM;

    uint32_t sbase = (uint32_t)__cvta_generic_to_shared(sm);

    auto load_tile = [&](int kb, int buf) {
        uint32_t as = sbase + (uint32_t)(buf * TILEW) * 4;
        uint32_t bs = sbase + (uint32_t)(2 * TILEW + buf * TILEW) * 4;
        #pragma unroll
        for (int j = 0; j < 4; j++) {
            int e = j * 256 + tid;          // 1024 float4 per tile
            int row = e >> 3, c4 = e & 7;   // 8 float4 per row of 32 floats
            cp16(as + (uint32_t)(row * PADW + c4 * 4) * 4,
                 Ag + (size_t)row * DIM + kb * BK + c4 * 4);
            cp16(bs + (uint32_t)(row * PADW + c4 * 4) * 4,
                 Bg + (size_t)row * DIM + kb * BK + c4 * 4);
        }
        asm volatile("cp.async.commit_group;" ::: "memory");
    };

    // warp grid 2(M) x 4(N): warp tile 64x32
    int wm = (wid & 1) * 64;
    int wn = (wid >> 1) * 32;
    float acc[4][4][4];
    #pragma unroll
    for (int mi = 0; mi < 4; mi++)
        #pragma unroll
        for (int ni = 0; ni < 4; ni++)
            #pragma unroll
            for (int q = 0; q < 4; q++) acc[mi][ni][q] = 0.f;

    load_tile(0, 0);
    const int NKB = DIM / BK;               // 16
    for (int kb = 0; kb < NKB; kb++) {
        if (kb + 1 < NKB) {
            load_tile(kb + 1, (kb + 1) & 1);
            asm volatile("cp.async.wait_group 1;" ::: "memory");
        } else {
            asm volatile("cp.async.wait_group 0;" ::: "memory");
        }
        __syncthreads();

        int buf = kb & 1;
        const uint32_t* As = (const uint32_t*)(sm + buf * TILEW);
        const uint32_t* Bs = (const uint32_t*)(sm + 2 * TILEW + buf * TILEW);
        int rq = lane >> 2, cq = lane & 3;
        #pragma unroll
        for (int ks = 0; ks < BK / 8; ks++) {
            int k0 = ks * 8;
            uint32_t bf[4][2];
            #pragma unroll
            for (int ni = 0; ni < 4; ni++) {
                int n = wn + ni * 8 + rq;
                bf[ni][0] = Bs[n * PADW + k0 + cq];
                bf[ni][1] = Bs[n * PADW + k0 + cq + 4];
            }
            #pragma unroll
            for (int mi = 0; mi < 4; mi++) {
                int r = wm + mi * 16 + rq;
                uint32_t fa0 = As[r * PADW + k0 + cq];
                uint32_t fa1 = As[(r + 8) * PADW + k0 + cq];
                uint32_t fa2 = As[r * PADW + k0 + cq + 4];
                uint32_t fa3 = As[(r + 8) * PADW + k0 + cq + 4];
                #pragma unroll
                for (int ni = 0; ni < 4; ni++)
                    mma_tf32(acc[mi][ni][0], acc[mi][ni][1], acc[mi][ni][2], acc[mi][ni][3],
                             fa0, fa1, fa2, fa3, bf[ni][0], bf[ni][1]);
            }
        }
        __syncthreads();
    }

    // epilogue: bias + store (f32 out)
    int rq = lane >> 2, cq = lane & 3;
    #pragma unroll
    for (int mi = 0; mi < 4; mi++) {
        int r0 = mtile * 128 + wm + mi * 16 + rq;
        #pragma unroll
        for (int ni = 0; ni < 4; ni++) {
            int col = ntile * 128 + wn + ni * 8 + 2 * cq;
            float2 bv = __ldg((const float2*)(linb + col));
            float2 v0 = {acc[mi][ni][0] + bv.x, acc[mi][ni][1] + bv.y};
            float2 v1 = {acc[mi][ni][2] + bv.x, acc[mi][ni][3] + bv.y};
            *(float2*)(out + (size_t)r0 * DIM + col) = v0;
            *(float2*)(out + (size_t)(r0 + 8) * DIM + col) = v1;
        }
    }
}

// ---------------- launch ----------------
extern "C" void kernel_launch(void* const* d_in, const int* in_sizes, int n_in,
                              void* d_out, int out_size) {
    const float* h     = (const float*)d_in[0];
    const float* w     = (const float*)d_in[1];
    const float* lin_w = (const float*)d_in[2];
    const float* lin_b = (const float*)d_in[3];
    const void*  idx   = d_in[4];
    float* out = (float*)d_out;

    zero_kernel<<<(NSEG + 255) / 256, 256>>>();
    detect_kernel<<<4, 256>>>((const unsigned int*)idx);
    hist_kernel<<<(NROWS + 255) / 256, 256>>>(idx);
    scan_kernel<<<1, 1024>>>();
    scatter_kernel<<<(NROWS + 255) / 256, 256>>>(idx);
    roundw_kernel<<<(DIM * DIM + 255) / 256, 256>>>(lin_w);
    gather_kernel<<<NSEG / 8, 256>>>(h, w);

    static int smem_set = 0;
    if (!smem_set) {
        cudaFuncSetAttribute(gemm_kernel, cudaFuncAttributeMaxDynamicSharedMemorySize,
                             SMEM_BYTES);
        smem_set = 1;
    }
    gemm_kernel<<<dim3(NSEG / 128, DIM / 128, 1), 256, SMEM_BYTES>>>(lin_b, out);
}

// round 4
// speedup vs baseline: 1.0659x; 1.0659x over previous
#include <cuda_runtime.h>
#include <cstdint>

#define NROWS 409600
#define NIN   51200
#define NSEG  65536
#define DIM   512

// ---------------- scratch (static __device__ arrays: alloc-free rule) ----------
__device__ int   g_is64 = 1;        // static init; detect only ever writes 0 -> replay-deterministic
__device__ int   g_counts[NSEG];
__device__ int   g_part[256];
__device__ int   g_pbase[256];
__device__ int   g_offsets[NSEG];
__device__ int   g_cursor[NSEG];
__device__ int   g_perm[NROWS];
__device__ float g_agg[(size_t)NSEG * DIM];     // 134 MB, tf32-rounded
__device__ float g_linw[DIM * DIM];             // tf32-rounded copy of lin_w

// ---------------- helpers ----------------
__device__ __forceinline__ float rna_tf32(float x) {
    uint32_t r;
    asm("cvt.rna.tf32.f32 %0, %1;" : "=r"(r) : "f"(x));
    return __uint_as_float(r);
}
__device__ __forceinline__ int load_idx(const void* idx, int i, int is64) {
    if (is64) return (int)((const long long*)idx)[i];
    return ((const int*)idx)[i];
}
__device__ __forceinline__ void cp16(uint32_t smem, const void* gmem) {
    asm volatile("cp.async.cg.shared.global [%0], [%1], 16;"
                 :: "r"(smem), "l"(gmem) : "memory");
}

// ---------------- prep kernels ----------------
// zero counts + int64/int32 detection (odd 32-bit words all zero <=> int64)
__global__ void zero_detect_kernel(const unsigned int* w32) {
    int i = blockIdx.x * blockDim.x + threadIdx.x;
    if (i < NSEG) g_counts[i] = 0;
    if (i < 1024 && w32[2 * i + 1] != 0u) g_is64 = 0;
}
__global__ void hist_kernel(const void* idx) {
    int i = blockIdx.x * blockDim.x + threadIdx.x;
    if (i >= NROWS) return;
    atomicAdd(&g_counts[load_idx(idx, i, g_is64)], 1);
}
// ---- parallel 3-stage exclusive scan of g_counts -> g_offsets/g_cursor ----
__global__ void scan1_kernel() {           // 256 blocks x 256 thr: chunk sums
    __shared__ int ws[8];
    int t = threadIdx.x;
    int v = g_counts[blockIdx.x * 256 + t];
    #pragma unroll
    for (int o = 16; o > 0; o >>= 1) v += __shfl_down_sync(0xFFFFFFFFu, v, o);
    if ((t & 31) == 0) ws[t >> 5] = v;
    __syncthreads();
    if (t == 0) {
        int s = 0;
        #pragma unroll
        for (int k = 0; k < 8; k++) s += ws[k];
        g_part[blockIdx.x] = s;
    }
}
__global__ void scan2_kernel() {           // 1 block x 256: exclusive scan of partials
    __shared__ int ws[8];
    int t = threadIdx.x, lane = t & 31, wid = t >> 5;
    int v = g_part[t];
    int x = v;
    #pragma unroll
    for (int o = 1; o < 32; o <<= 1) {
        int y = __shfl_up_sync(0xFFFFFFFFu, x, o);
        if (lane >= o) x += y;
    }
    if (lane == 31) ws[wid] = x;
    __syncthreads();
    if (t < 8) {
        int s = ws[t];
        #pragma unroll
        for (int o = 1; o < 8; o <<= 1) {
            int y = __shfl_up_sync(0xFFu, s, o);
            if (t >= o) s += y;
        }
        ws[t] = s;
    }
    __syncthreads();
    int base = (wid > 0) ? ws[wid - 1] : 0;
    g_pbase[t] = base + x - v;             // exclusive
}
__global__ void scan3_kernel() {           // 256 blocks x 256: in-chunk exclusive + base
    __shared__ int ws[8];
    int t = threadIdx.x, lane = t & 31, wid = t >> 5;
    int i = blockIdx.x * 256 + t;
    int v = g_counts[i];
    int x = v;
    #pragma unroll
    for (int o = 1; o < 32; o <<= 1) {
        int y = __shfl_up_sync(0xFFFFFFFFu, x, o);
        if (lane >= o) x += y;
    }
    if (lane == 31) ws[wid] = x;
    __syncthreads();
    if (t < 8) {
        int s = ws[t];
        #pragma unroll
        for (int o = 1; o < 8; o <<= 1) {
            int y = __shfl_up_sync(0xFFu, s, o);
            if (t >= o) s += y;
        }
        ws[t] = s;
    }
    __syncthreads();
    int base = (wid > 0) ? ws[wid - 1] : 0;
    int off = g_pbase[blockIdx.x] + base + x - v;
    g_offsets[i] = off;
    g_cursor[i]  = off;
}
__global__ void scatter_kernel(const void* idx) {
    int i = blockIdx.x * blockDim.x + threadIdx.x;
    if (i >= NROWS) return;
    int s = load_idx(idx, i, g_is64);
    int pos = atomicAdd(&g_cursor[s], 1);
    g_perm[pos] = i;
}
__global__ void roundw_kernel(const float* __restrict__ lw) {
    int i = blockIdx.x * blockDim.x + threadIdx.x;
    if (i < DIM * DIM) g_linw[i] = rna_tf32(lw[i]);
}

// ---------------- gather-sum: one warp per segment, deterministic order --------
__global__ void __launch_bounds__(256) gather_kernel(const float* __restrict__ h,
                                                     const float* __restrict__ w) {
    int warp = (blockIdx.x * blockDim.x + threadIdx.x) >> 5;
    int lane = threadIdx.x & 31;
    if (warp >= NSEG) return;
    int start = g_offsets[warp];
    int cnt   = g_counts[warp];
    float4 a0 = {0.f, 0.f, 0.f, 0.f}, a1 = a0, a2 = a0, a3 = a0;
    const float4* hb = (const float4*)h;

    auto accum = [&](int row) {
        float wv = __ldg(&w[row % NIN]);
        const float4* hp = hb + (size_t)row * (DIM / 4);
        float4 v0 = __ldg(hp + lane);
        float4 v1 = __ldg(hp + 32 + lane);
        float4 v2 = __ldg(hp + 64 + lane);
        float4 v3 = __ldg(hp + 96 + lane);
        a0.x = fmaf(wv, v0.x, a0.x); a0.y = fmaf(wv, v0.y, a0.y);
        a0.z = fmaf(wv, v0.z, a0.z); a0.w = fmaf(wv, v0.w, a0.w);
        a1.x = fmaf(wv, v1.x, a1.x); a1.y = fmaf(wv, v1.y, a1.y);
        a1.z = fmaf(wv, v1.z, a1.z); a1.w = fmaf(wv, v1.w, a1.w);
        a2.x = fmaf(wv, v2.x, a2.x); a2.y = fmaf(wv, v2.y, a2.y);
        a2.z = fmaf(wv, v2.z, a2.z); a2.w = fmaf(wv, v2.w, a2.w);
        a3.x = fmaf(wv, v3.x, a3.x); a3.y = fmaf(wv, v3.y, a3.y);
        a3.z = fmaf(wv, v3.z, a3.z); a3.w = fmaf(wv, v3.w, a3.w);
    };

    if (cnt <= 256) {
        // ascending-row min-extraction => replay-deterministic fp32 order
        int vals[8];
        int nslot = (cnt + 31) >> 5;
        #pragma unroll
        for (int t = 0; t < 8; t++) {
            int p = t * 32 + lane;
            vals[t] = (t < nslot && p < cnt) ? g_perm[start + p] : 0x7FFFFFFF;
        }
        for (int it = 0; it < cnt; it++) {
            int m = 0x7FFFFFFF, mt = -1;
            #pragma unroll
            for (int t = 0; t < 8; t++)
                if (vals[t] < m) { m = vals[t]; mt = t; }
            int gm = __reduce_min_sync(0xFFFFFFFFu, m);
            if (m == gm && mt >= 0) vals[mt] = 0x7FFFFFFF;  // rows unique: one owner
            accum(gm);
        }
    } else {
        for (int j = 0; j < cnt; j++) accum(g_perm[start + j]);
    }

    float4* dst = (float4*)(g_agg + (size_t)warp * DIM);
    float4 o;
    o.x = rna_tf32(a0.x); o.y = rna_tf32(a0.y); o.z = rna_tf32(a0.z); o.w = rna_tf32(a0.w);
    dst[lane] = o;
    o.x = rna_tf32(a1.x); o.y = rna_tf32(a1.y); o.z = rna_tf32(a1.z); o.w = rna_tf32(a1.w);
    dst[32 + lane] = o;
    o.x = rna_tf32(a2.x); o.y = rna_tf32(a2.y); o.z = rna_tf32(a2.z); o.w = rna_tf32(a2.w);
    dst[64 + lane] = o;
    o.x = rna_tf32(a3.x); o.y = rna_tf32(a3.y); o.z = rna_tf32(a3.z); o.w = rna_tf32(a3.w);
    dst[96 + lane] = o;
}

// ---------------- tf32 mma.sync GEMM: out = agg @ lin_w^T + b -------------------
// BM=128, BN=256, BK=32, 512 threads (16 warps, 2Mx8N grid, warp tile 64x32).
// Smem rows padded to 36 words => conflict-free fragment LDS.
#define BK 32
#define PADW 36
#define ATILEW (128 * PADW)
#define BTILEW (256 * PADW)
#define SMEM_BYTES ((2 * ATILEW + 2 * BTILEW) * 4)   // 110592

__device__ __forceinline__ void mma_tf32(float& d0, float& d1, float& d2, float& d3,
                                         uint32_t a0, uint32_t a1, uint32_t a2, uint32_t a3,
                                         uint32_t b0, uint32_t b1) {
    asm volatile(
        "mma.sync.aligned.m16n8k8.row.col.f32.tf32.tf32.f32 "
        "{%0,%1,%2,%3}, {%4,%5,%6,%7}, {%8,%9}, {%0,%1,%2,%3};"
        : "+f"(d0), "+f"(d1), "+f"(d2), "+f"(d3)
        : "r"(a0), "r"(a1), "r"(a2), "r"(a3), "r"(b0), "r"(b1));
}

__global__ void __launch_bounds__(512, 1)
gemm_kernel(const float* __restrict__ linb, float* __restrict__ out) {
    extern __shared__ float sm[];
    int tid = threadIdx.x, lane = tid & 31, wid = tid >> 5;
    int mtile = blockIdx.x, ntile = blockIdx.y;
    const float* Ag = g_agg  + (size_t)mtile * 128 * DIM;
    const float* Bg = g_linw + (size_t)ntile * 256 * DIM;

    uint32_t sbase = (uint32_t)__cvta_generic_to_shared(sm);

    auto load_tile = [&](int kb, int buf) {
        uint32_t as = sbase + (uint32_t)(buf * ATILEW) * 4;
        uint32_t bs = sbase + (uint32_t)(2 * ATILEW + buf * BTILEW) * 4;
        #pragma unroll
        for (int j = 0; j < 2; j++) {            // A: 128x32 = 1024 float4
            int e = j * 512 + tid;
            int row = e >> 3, c4 = e & 7;
            cp16(as + (uint32_t)(row * PADW + c4 * 4) * 4,
                 Ag + (size_t)row * DIM + kb * BK + c4 * 4);
        }
        #pragma unroll
        for (int j = 0; j < 4; j++) {            // B: 256x32 = 2048 float4
            int e = j * 512 + tid;
            int row = e >> 3, c4 = e & 7;
            cp16(bs + (uint32_t)(row * PADW + c4 * 4) * 4,
                 Bg + (size_t)row * DIM + kb * BK + c4 * 4);
        }
        asm volatile("cp.async.commit_group;" ::: "memory");
    };

    int wm = (wid & 1) * 64;                     // 2 M-positions
    int wn = (wid >> 1) * 32;                    // 8 N-positions -> 256
    float acc[4][4][4];
    #pragma unroll
    for (int mi = 0; mi < 4; mi++)
        #pragma unroll
        for (int ni = 0; ni < 4; ni++)
            #pragma unroll
            for (int q = 0; q < 4; q++) acc[mi][ni][q] = 0.f;

    load_tile(0, 0);
    const int NKB = DIM / BK;                    // 16
    for (int kb = 0; kb < NKB; kb++) {
        if (kb + 1 < NKB) {
            load_tile(kb + 1, (kb + 1) & 1);
            asm volatile("cp.async.wait_group 1;" ::: "memory");
        } else {
            asm volatile("cp.async.wait_group 0;" ::: "memory");
        }
        __syncthreads();

        int buf = kb & 1;
        const uint32_t* As = (const uint32_t*)(sm + buf * ATILEW);
        const uint32_t* Bs = (const uint32_t*)(sm + 2 * ATILEW + buf * BTILEW);
        int rq = lane >> 2, cq = lane & 3;
        #pragma unroll
        for (int ks = 0; ks < BK / 8; ks++) {
            int k0 = ks * 8;
            uint32_t bf[4][2];
            #pragma unroll
            for (int ni = 0; ni < 4; ni++) {
                int n = wn + ni * 8 + rq;
                bf[ni][0] = Bs[n * PADW + k0 + cq];
                bf[ni][1] = Bs[n * PADW + k0 + cq + 4];
            }
            #pragma unroll
            for (int mi = 0; mi < 4; mi++) {
                int r = wm + mi * 16 + rq;
                uint32_t fa0 = As[r * PADW + k0 + cq];
                uint32_t fa1 = As[(r + 8) * PADW + k0 + cq];
                uint32_t fa2 = As[r * PADW + k0 + cq + 4];
                uint32_t fa3 = As[(r + 8) * PADW + k0 + cq + 4];
                #pragma unroll
                for (int ni = 0; ni < 4; ni++)
                    mma_tf32(acc[mi][ni][0], acc[mi][ni][1], acc[mi][ni][2], acc[mi][ni][3],
                             fa0, fa1, fa2, fa3, bf[ni][0], bf[ni][1]);
            }
        }
        __syncthreads();
    }

    // epilogue: bias + store (f32 out)
    int rq = lane >> 2, cq = lane & 3;
    #pragma unroll
    for (int mi = 0; mi < 4; mi++) {
        int r0 = mtile * 128 + wm + mi * 16 + rq;
        #pragma unroll
        for (int ni = 0; ni < 4; ni++) {
            int col = ntile * 256 + wn + ni * 8 + 2 * cq;
            float2 bv = __ldg((const float2*)(linb + col));
            float2 v0 = {acc[mi][ni][0] + bv.x, acc[mi][ni][1] + bv.y};
            float2 v1 = {acc[mi][ni][2] + bv.x, acc[mi][ni][3] + bv.y};
            *(float2*)(out + (size_t)r0 * DIM + col) = v0;
            *(float2*)(out + (size_t)(r0 + 8) * DIM + col) = v1;
        }
    }
}

// ---------------- launch ----------------
extern "C" void kernel_launch(void* const* d_in, const int* in_sizes, int n_in,
                              void* d_out, int out_size) {
    const float* h     = (const float*)d_in[0];
    const float* w     = (const float*)d_in[1];
    const float* lin_w = (const float*)d_in[2];
    const float* lin_b = (const float*)d_in[3];
    const void*  idx   = d_in[4];
    float* out = (float*)d_out;

    zero_detect_kernel<<<(NSEG + 255) / 256, 256>>>((const unsigned int*)idx);
    hist_kernel<<<(NROWS + 255) / 256, 256>>>(idx);
    scan1_kernel<<<256, 256>>>();
    scan2_kernel<<<1, 256>>>();
    scan3_kernel<<<256, 256>>>();
    scatter_kernel<<<(NROWS + 255) / 256, 256>>>(idx);
    roundw_kernel<<<(DIM * DIM + 255) / 256, 256>>>(lin_w);
    gather_kernel<<<NSEG / 8, 256>>>(h, w);

    static int smem_set = 0;
    if (!smem_set) {
        cudaFuncSetAttribute(gemm_kernel, cudaFuncAttributeMaxDynamicSharedMemorySize,
                             SMEM_BYTES);
        smem_set = 1;
    }
    gemm_kernel<<<dim3(NSEG / 128, DIM / 256, 1), 512, SMEM_BYTES>>>(lin_b, out);
}

// round 5
// speedup vs baseline: 1.0954x; 1.0276x over previous
#include <cuda_runtime.h>
#include <cstdint>

#define NROWS 409600
#define NIN   51200
#define NSEG  65536
#define DIM   512

// ---------------- scratch (static __device__ arrays: alloc-free rule) ----------
__device__ int   g_is64 = 1;        // detect only ever writes 0 -> replay-deterministic
__device__ int   g_counts[NSEG];
__device__ int   g_part[256];
__device__ int   g_pbase[256];
__device__ int   g_offsets[NSEG];
__device__ int   g_cursor[NSEG];
__device__ int   g_perm[NROWS];
__device__ float g_agg[(size_t)NSEG * DIM];     // 134 MB, tf32-rounded
__device__ float g_linw[DIM * DIM];             // tf32-rounded copy of lin_w

// ---------------- helpers ----------------
__device__ __forceinline__ float rna_tf32(float x) {
    uint32_t r;
    asm("cvt.rna.tf32.f32 %0, %1;" : "=r"(r) : "f"(x));
    return __uint_as_float(r);
}
__device__ __forceinline__ int load_idx(const void* idx, int i, int is64) {
    if (is64) return (int)((const long long*)idx)[i];
    return ((const int*)idx)[i];
}
__device__ __forceinline__ void cp16(uint32_t smem, const void* gmem) {
    asm volatile("cp.async.cg.shared.global [%0], [%1], 16;"
                 :: "r"(smem), "l"(gmem) : "memory");
}

// ---------------- prep kernels ----------------
__global__ void zero_detect_kernel(const unsigned int* w32) {
    int i = blockIdx.x * blockDim.x + threadIdx.x;
    if (i < NSEG) g_counts[i] = 0;
    if (i < 1024 && w32[2 * i + 1] != 0u) g_is64 = 0;
}
__global__ void hist_kernel(const void* idx) {
    int i = blockIdx.x * blockDim.x + threadIdx.x;
    if (i >= NROWS) return;
    atomicAdd(&g_counts[load_idx(idx, i, g_is64)], 1);
}
// ---- parallel 3-stage exclusive scan ----
__global__ void scan1_kernel() {
    __shared__ int ws[8];
    int t = threadIdx.x;
    int v = g_counts[blockIdx.x * 256 + t];
    #pragma unroll
    for (int o = 16; o > 0; o >>= 1) v += __shfl_down_sync(0xFFFFFFFFu, v, o);
    if ((t & 31) == 0) ws[t >> 5] = v;
    __syncthreads();
    if (t == 0) {
        int s = 0;
        #pragma unroll
        for (int k = 0; k < 8; k++) s += ws[k];
        g_part[blockIdx.x] = s;
    }
}
__global__ void scan2_kernel() {
    __shared__ int ws[8];
    int t = threadIdx.x, lane = t & 31, wid = t >> 5;
    int v = g_part[t];
    int x = v;
    #pragma unroll
    for (int o = 1; o < 32; o <<= 1) {
        int y = __shfl_up_sync(0xFFFFFFFFu, x, o);
        if (lane >= o) x += y;
    }
    if (lane == 31) ws[wid] = x;
    __syncthreads();
    if (t < 8) {
        int s = ws[t];
        #pragma unroll
        for (int o = 1; o < 8; o <<= 1) {
            int y = __shfl_up_sync(0xFFu, s, o);
            if (t >= o) s += y;
        }
        ws[t] = s;
    }
    __syncthreads();
    int base = (wid > 0) ? ws[wid - 1] : 0;
    g_pbase[t] = base + x - v;
}
__global__ void scan3_kernel() {
    __shared__ int ws[8];
    int t = threadIdx.x, lane = t & 31, wid = t >> 5;
    int i = blockIdx.x * 256 + t;
    int v = g_counts[i];
    int x = v;
    #pragma unroll
    for (int o = 1; o < 32; o <<= 1) {
        int y = __shfl_up_sync(0xFFFFFFFFu, x, o);
        if (lane >= o) x += y;
    }
    if (lane == 31) ws[wid] = x;
    __syncthreads();
    if (t < 8) {
        int s = ws[t];
        #pragma unroll
        for (int o = 1; o < 8; o <<= 1) {
            int y = __shfl_up_sync(0xFFu, s, o);
            if (t >= o) s += y;
        }
        ws[t] = s;
    }
    __syncthreads();
    int base = (wid > 0) ? ws[wid - 1] : 0;
    int off = g_pbase[blockIdx.x] + base + x - v;
    g_offsets[i] = off;
    g_cursor[i]  = off;
}
__global__ void scatter_kernel(const void* idx) {
    int i = blockIdx.x * blockDim.x + threadIdx.x;
    if (i >= NROWS) return;
    int s = load_idx(idx, i, g_is64);
    int pos = atomicAdd(&g_cursor[s], 1);
    g_perm[pos] = i;
}
__global__ void roundw_kernel(const float* __restrict__ lw) {
    int i = blockIdx.x * blockDim.x + threadIdx.x;
    if (i < DIM * DIM) g_linw[i] = rna_tf32(lw[i]);
}

// ---------------- gather-sum: one warp per segment, deterministic order --------
__global__ void __launch_bounds__(256) gather_kernel(const float* __restrict__ h,
                                                     const float* __restrict__ w) {
    int warp = (blockIdx.x * blockDim.x + threadIdx.x) >> 5;
    int lane = threadIdx.x & 31;
    if (warp >= NSEG) return;
    int start = g_offsets[warp];
    int cnt   = g_counts[warp];
    float4 a0 = {0.f, 0.f, 0.f, 0.f}, a1 = a0, a2 = a0, a3 = a0;
    const float4* hb = (const float4*)h;

    auto accum2 = [&](int rowA, int rowB) {   // rowB < 0 => single
        float wv0 = __ldg(&w[rowA % NIN]);
        const float4* hp0 = hb + (size_t)rowA * (DIM / 4);
        float4 x0 = __ldg(hp0 + lane);
        float4 x1 = __ldg(hp0 + 32 + lane);
        float4 x2 = __ldg(hp0 + 64 + lane);
        float4 x3 = __ldg(hp0 + 96 + lane);
        float wv1 = 0.f;
        float4 y0 = x0, y1 = x1, y2 = x2, y3 = x3;
        if (rowB >= 0) {
            wv1 = __ldg(&w[rowB % NIN]);
            const float4* hp1 = hb + (size_t)rowB * (DIM / 4);
            y0 = __ldg(hp1 + lane);
            y1 = __ldg(hp1 + 32 + lane);
            y2 = __ldg(hp1 + 64 + lane);
            y3 = __ldg(hp1 + 96 + lane);
        }
        a0.x = fmaf(wv0, x0.x, a0.x); a0.y = fmaf(wv0, x0.y, a0.y);
        a0.z = fmaf(wv0, x0.z, a0.z); a0.w = fmaf(wv0, x0.w, a0.w);
        a1.x = fmaf(wv0, x1.x, a1.x); a1.y = fmaf(wv0, x1.y, a1.y);
        a1.z = fmaf(wv0, x1.z, a1.z); a1.w = fmaf(wv0, x1.w, a1.w);
        a2.x = fmaf(wv0, x2.x, a2.x); a2.y = fmaf(wv0, x2.y, a2.y);
        a2.z = fmaf(wv0, x2.z, a2.z); a2.w = fmaf(wv0, x2.w, a2.w);
        a3.x = fmaf(wv0, x3.x, a3.x); a3.y = fmaf(wv0, x3.y, a3.y);
        a3.z = fmaf(wv0, x3.z, a3.z); a3.w = fmaf(wv0, x3.w, a3.w);
        if (rowB >= 0) {
            a0.x = fmaf(wv1, y0.x, a0.x); a0.y = fmaf(wv1, y0.y, a0.y);
            a0.z = fmaf(wv1, y0.z, a0.z); a0.w = fmaf(wv1, y0.w, a0.w);
            a1.x = fmaf(wv1, y1.x, a1.x); a1.y = fmaf(wv1, y1.y, a1.y);
            a1.z = fmaf(wv1, y1.z, a1.z); a1.w = fmaf(wv1, y1.w, a1.w);
            a2.x = fmaf(wv1, y2.x, a2.x); a2.y = fmaf(wv1, y2.y, a2.y);
            a2.z = fmaf(wv1, y2.z, a2.z); a2.w = fmaf(wv1, y2.w, a2.w);
            a3.x = fmaf(wv1, y3.x, a3.x); a3.y = fmaf(wv1, y3.y, a3.y);
            a3.z = fmaf(wv1, y3.z, a3.z); a3.w = fmaf(wv1, y3.w, a3.w);
        }
    };

    if (cnt <= 32) {
        // 32-lane bitonic sort of row ids (ascending): deterministic order,
        // and all rows known before any load -> deep MLP in the accumulate loop.
        int v = (lane < cnt) ? g_perm[start + lane] : 0x7FFFFFFF;
        #pragma unroll
        for (int k = 2; k <= 32; k <<= 1) {
            #pragma unroll
            for (int j = k >> 1; j > 0; j >>= 1) {
                int p = __shfl_xor_sync(0xFFFFFFFFu, v, j);
                bool up = ((lane & k) == 0);
                bool lower = ((lane & j) == 0);
                v = (lower == up) ? min(v, p) : max(v, p);
            }
        }
        int j = 0;
        for (; j + 2 <= cnt; j += 2) {
            int rA = __shfl_sync(0xFFFFFFFFu, v, j);
            int rB = __shfl_sync(0xFFFFFFFFu, v, j + 1);
            accum2(rA, rB);
        }
        if (j < cnt) accum2(__shfl_sync(0xFFFFFFFFu, v, j), -1);
    } else if (cnt <= 256) {
        // min-extraction fallback (rare)
        int vals[8];
        int nslot = (cnt + 31) >> 5;
        #pragma unroll
        for (int t = 0; t < 8; t++) {
            int p = t * 32 + lane;
            vals[t] = (t < nslot && p < cnt) ? g_perm[start + p] : 0x7FFFFFFF;
        }
        for (int it = 0; it < cnt; it++) {
            int m = 0x7FFFFFFF, mt = -1;
            #pragma unroll
            for (int t = 0; t < 8; t++)
                if (vals[t] < m) { m = vals[t]; mt = t; }
            int gm = __reduce_min_sync(0xFFFFFFFFu, m);
            if (m == gm && mt >= 0) vals[mt] = 0x7FFFFFFF;
            accum2(gm, -1);
        }
    } else {
        for (int j = 0; j < cnt; j++) accum2(g_perm[start + j], -1);
    }

    float4* dst = (float4*)(g_agg + (size_t)warp * DIM);
    float4 o;
    o.x = rna_tf32(a0.x); o.y = rna_tf32(a0.y); o.z = rna_tf32(a0.z); o.w = rna_tf32(a0.w);
    dst[lane] = o;
    o.x = rna_tf32(a1.x); o.y = rna_tf32(a1.y); o.z = rna_tf32(a1.z); o.w = rna_tf32(a1.w);
    dst[32 + lane] = o;
    o.x = rna_tf32(a2.x); o.y = rna_tf32(a2.y); o.z = rna_tf32(a2.z); o.w = rna_tf32(a2.w);
    dst[64 + lane] = o;
    o.x = rna_tf32(a3.x); o.y = rna_tf32(a3.y); o.z = rna_tf32(a3.z); o.w = rna_tf32(a3.w);
    dst[96 + lane] = o;
}

// ---------------- tf32 mma.sync GEMM: out = agg @ lin_w^T + b -------------------
// BM=128, BN=256, BK=32, 512 threads. Grid = (ntile, mtile) so both ntile blocks
// of one mtile are co-resident -> A-tile second read hits L2 instead of DRAM.
#define BK 32
#define PADW 36
#define ATILEW (128 * PADW)
#define BTILEW (256 * PADW)
#define SMEM_BYTES ((2 * ATILEW + 2 * BTILEW) * 4)   // 110592

__device__ __forceinline__ void mma_tf32(float& d0, float& d1, float& d2, float& d3,
                                         uint32_t a0, uint32_t a1, uint32_t a2, uint32_t a3,
                                         uint32_t b0, uint32_t b1) {
    asm volatile(
        "mma.sync.aligned.m16n8k8.row.col.f32.tf32.tf32.f32 "
        "{%0,%1,%2,%3}, {%4,%5,%6,%7}, {%8,%9}, {%0,%1,%2,%3};"
        : "+f"(d0), "+f"(d1), "+f"(d2), "+f"(d3)
        : "r"(a0), "r"(a1), "r"(a2), "r"(a3), "r"(b0), "r"(b1));
}

__global__ void __launch_bounds__(512, 1)
gemm_kernel(const float* __restrict__ linb, float* __restrict__ out) {
    extern __shared__ float sm[];
    int tid = threadIdx.x, lane = tid & 31, wid = tid >> 5;
    int ntile = blockIdx.x, mtile = blockIdx.y;
    const float* Ag = g_agg  + (size_t)mtile * 128 * DIM;
    const float* Bg = g_linw + (size_t)ntile * 256 * DIM;

    uint32_t sbase = (uint32_t)__cvta_generic_to_shared(sm);

    auto load_tile = [&](int kb, int buf) {
        uint32_t as = sbase + (uint32_t)(buf * ATILEW) * 4;
        uint32_t bs = sbase + (uint32_t)(2 * ATILEW + buf * BTILEW) * 4;
        #pragma unroll
        for (int j = 0; j < 2; j++) {            // A: 128x32 = 1024 float4
            int e = j * 512 + tid;
            int row = e >> 3, c4 = e & 7;
            cp16(as + (uint32_t)(row * PADW + c4 * 4) * 4,
                 Ag + (size_t)row * DIM + kb * BK + c4 * 4);
        }
        #pragma unroll
        for (int j = 0; j < 4; j++) {            // B: 256x32 = 2048 float4
            int e = j * 512 + tid;
            int row = e >> 3, c4 = e & 7;
            cp16(bs + (uint32_t)(row * PADW + c4 * 4) * 4,
                 Bg + (size_t)row * DIM + kb * BK + c4 * 4);
        }
        asm volatile("cp.async.commit_group;" ::: "memory");
    };

    int wm = (wid & 1) * 64;
    int wn = (wid >> 1) * 32;
    float acc[4][4][4];
    #pragma unroll
    for (int mi = 0; mi < 4; mi++)
        #pragma unroll
        for (int ni = 0; ni < 4; ni++)
            #pragma unroll
            for (int q = 0; q < 4; q++) acc[mi][ni][q] = 0.f;

    load_tile(0, 0);
    const int NKB = DIM / BK;
    for (int kb = 0; kb < NKB; kb++) {
        if (kb + 1 < NKB) {
            load_tile(kb + 1, (kb + 1) & 1);
            asm volatile("cp.async.wait_group 1;" ::: "memory");
        } else {
            asm volatile("cp.async.wait_group 0;" ::: "memory");
        }
        __syncthreads();

        int buf = kb & 1;
        const uint32_t* As = (const uint32_t*)(sm + buf * ATILEW);
        const uint32_t* Bs = (const uint32_t*)(sm + 2 * ATILEW + buf * BTILEW);
        int rq = lane >> 2, cq = lane & 3;
        #pragma unroll
        for (int ks = 0; ks < BK / 8; ks++) {
            int k0 = ks * 8;
            uint32_t bf[4][2];
            #pragma unroll
            for (int ni = 0; ni < 4; ni++) {
                int n = wn + ni * 8 + rq;
                bf[ni][0] = Bs[n * PADW + k0 + cq];
                bf[ni][1] = Bs[n * PADW + k0 + cq + 4];
            }
            #pragma unroll
            for (int mi = 0; mi < 4; mi++) {
                int r = wm + mi * 16 + rq;
                uint32_t fa0 = As[r * PADW + k0 + cq];
                uint32_t fa1 = As[(r + 8) * PADW + k0 + cq];
                uint32_t fa2 = As[r * PADW + k0 + cq + 4];
                uint32_t fa3 = As[(r + 8) * PADW + k0 + cq + 4];
                #pragma unroll
                for (int ni = 0; ni < 4; ni++)
                    mma_tf32(acc[mi][ni][0], acc[mi][ni][1], acc[mi][ni][2], acc[mi][ni][3],
                             fa0, fa1, fa2, fa3, bf[ni][0], bf[ni][1]);
            }
        }
        __syncthreads();
    }

    int rq = lane >> 2, cq = lane & 3;
    #pragma unroll
    for (int mi = 0; mi < 4; mi++) {
        int r0 = mtile * 128 + wm + mi * 16 + rq;
        #pragma unroll
        for (int ni = 0; ni < 4; ni++) {
            int col = ntile * 256 + wn + ni * 8 + 2 * cq;
            float2 bv = __ldg((const float2*)(linb + col));
            float2 v0 = {acc[mi][ni][0] + bv.x, acc[mi][ni][1] + bv.y};
            float2 v1 = {acc[mi][ni][2] + bv.x, acc[mi][ni][3] + bv.y};
            *(float2*)(out + (size_t)r0 * DIM + col) = v0;
            *(float2*)(out + (size_t)(r0 + 8) * DIM + col) = v1;
        }
    }
}

// ---------------- launch ----------------
extern "C" void kernel_launch(void* const* d_in, const int* in_sizes, int n_in,
                              void* d_out, int out_size) {
    const float* h     = (const float*)d_in[0];
    const float* w     = (const float*)d_in[1];
    const float* lin_w = (const float*)d_in[2];
    const float* lin_b = (const float*)d_in[3];
    const void*  idx   = d_in[4];
    float* out = (float*)d_out;

    zero_detect_kernel<<<(NSEG + 255) / 256, 256>>>((const unsigned int*)idx);
    hist_kernel<<<(NROWS + 255) / 256, 256>>>(idx);
    scan1_kernel<<<256, 256>>>();
    scan2_kernel<<<1, 256>>>();
    scan3_kernel<<<256, 256>>>();
    scatter_kernel<<<(NROWS + 255) / 256, 256>>>(idx);
    roundw_kernel<<<(DIM * DIM + 255) / 256, 256>>>(lin_w);
    gather_kernel<<<NSEG / 8, 256>>>(h, w);

    static int smem_set = 0;
    if (!smem_set) {
        cudaFuncSetAttribute(gemm_kernel, cudaFuncAttributeMaxDynamicSharedMemorySize,
                             SMEM_BYTES);
        smem_set = 1;
    }
    gemm_kernel<<<dim3(DIM / 256, NSEG / 128, 1), 512, SMEM_BYTES>>>(lin_b, out);
}